// round 11
// baseline (speedup 1.0000x reference)
#include <cuda_runtime.h>
#include <cuda_bf16.h>
#include <cstdint>

// Problem constants (fixed by the dataset)
#define NN   50000
#define EE   800000
#define NFK  256
#define HD   128
#define NL   3

typedef unsigned long long ull;

// Scratch: static device arrays (no runtime allocation allowed)
__device__ __align__(16) float g_aggf[NN * HD];          // fp32 GEMM input (25.6 MB)
__device__ __align__(16) __nv_bfloat16 g_h0[NN * HD];    // bf16 h ping
__device__ __align__(16) __nv_bfloat16 g_h1[NN * HD];    // bf16 h pong
__device__ float g_colsum[(NL + 1) * HD];                // 512 floats
// CSR scratch
__device__ int   g_cnt[NN];
__device__ int   g_rowptr[NN + 1];
__device__ int   g_offs[NN];
__device__ int   g_esrc[EE];
__device__ float g_rscale[EE];

// ---------------------------------------------------------------------------
// low-level helpers
// ---------------------------------------------------------------------------
__device__ __forceinline__ uint32_t smem_u32(const void* p) {
    uint32_t a;
    asm("{ .reg .u64 tmp; cvta.to.shared.u64 tmp, %1; cvt.u32.u64 %0, tmp; }"
        : "=r"(a) : "l"(p));
    return a;
}
__device__ __forceinline__ void ldsm4(unsigned* r, uint32_t addr) {
    asm volatile("ldmatrix.sync.aligned.m8n8.x4.shared.b16 {%0,%1,%2,%3}, [%4];"
        : "=r"(r[0]), "=r"(r[1]), "=r"(r[2]), "=r"(r[3]) : "r"(addr));
}
__device__ __forceinline__ void mma16816(float* c, const unsigned* a, const unsigned* b) {
    asm volatile("mma.sync.aligned.m16n8k16.row.col.f32.bf16.bf16.f32 "
        "{%0,%1,%2,%3}, {%4,%5,%6,%7}, {%8,%9}, {%0,%1,%2,%3};"
        : "+f"(c[0]), "+f"(c[1]), "+f"(c[2]), "+f"(c[3])
        : "r"(a[0]), "r"(a[1]), "r"(a[2]), "r"(a[3]), "r"(b[0]), "r"(b[1]));
}
// pack two fp32 into bf16x2 (hi parts)
__device__ __forceinline__ unsigned pk_hi(float a, float b) {
    __nv_bfloat162 p = __floats2bfloat162_rn(a, b);
    return *reinterpret_cast<unsigned*>(&p);
}
// pack the residual lo parts of two fp32
__device__ __forceinline__ unsigned pk_lo(float a, float b) {
    float ah = __bfloat162float(__float2bfloat16_rn(a));
    float bh = __bfloat162float(__float2bfloat16_rn(b));
    __nv_bfloat162 p = __floats2bfloat162_rn(a - ah, b - bh);
    return *reinterpret_cast<unsigned*>(&p);
}

// ---------------------------------------------------------------------------
// CSR build (per replay; order within a dst bucket is arbitrary)
// ---------------------------------------------------------------------------
__global__ void hist_kernel(const int* __restrict__ dst, int e)
{
    int i = blockIdx.x * blockDim.x + threadIdx.x;
    if (i < e) atomicAdd(&g_cnt[dst[i]], 1);
}

__global__ __launch_bounds__(1024)
void scan_kernel(int n)
{
    __shared__ int part[1024];
    int t = threadIdx.x;
    int chunk = (n + 1023) >> 10;
    int beg = t * chunk, end = min(beg + chunk, n);
    int s = 0;
    for (int i = beg; i < end; i++) s += g_cnt[i];
    part[t] = s;
    __syncthreads();
    for (int off = 1; off < 1024; off <<= 1) {
        int v = (t >= off) ? part[t - off] : 0;
        __syncthreads();
        part[t] += v;
        __syncthreads();
    }
    int run = part[t] - s;
    for (int i = beg; i < end; i++) {
        g_rowptr[i] = run;
        g_offs[i]   = run;
        run += g_cnt[i];
    }
    if (end == n) g_rowptr[n] = run;
}

__global__ void fill_kernel(const int* __restrict__ src, const int* __restrict__ dst,
                            const float* __restrict__ degree, int e)
{
    int i = blockIdx.x * blockDim.x + threadIdx.x;
    if (i >= e) return;
    int s = src[i], d = dst[i];
    int pos = atomicAdd(&g_offs[d], 1);
    g_esrc[pos]   = s;
    g_rscale[pos] = 1.0f / degree[s];
}

// ---------------------------------------------------------------------------
// Gather over bf16 hidden states, fp32 accumulation.
// MODE 0: out_bf16[v] = sum_{u->v} h[u]
// MODE 1: out_f32[v]  = h[v] + sum_{u->v} h[u] * (1/deg[u])
// ---------------------------------------------------------------------------
__device__ __forceinline__ void acc_bf(float4& acc, ull x, float c)
{
    const __nv_bfloat162* p = reinterpret_cast<const __nv_bfloat162*>(&x);
    float2 f0 = __bfloat1622float2(p[0]);
    float2 f1 = __bfloat1622float2(p[1]);
    acc.x = fmaf(f0.x, c, acc.x); acc.y = fmaf(f0.y, c, acc.y);
    acc.z = fmaf(f1.x, c, acc.z); acc.w = fmaf(f1.y, c, acc.w);
}

template <int MODE>
__global__ __launch_bounds__(256)
void gather_kernel(const ull* __restrict__ h, void* __restrict__ out_, int n)
{
    int w    = (blockIdx.x * blockDim.x + threadIdx.x) >> 5;
    int lane = threadIdx.x & 31;
    if (w >= n) return;
    int beg = g_rowptr[w], end = g_rowptr[w + 1];

    float4 acc = make_float4(0.f, 0.f, 0.f, 0.f);
    if (MODE) acc_bf(acc, h[(size_t)w * 32 + lane], 1.0f);

    int i = beg;
    for (; i + 4 <= end; i += 4) {
        int s0 = g_esrc[i], s1 = g_esrc[i + 1], s2 = g_esrc[i + 2], s3 = g_esrc[i + 3];
        ull x0 = h[(size_t)s0 * 32 + lane];
        ull x1 = h[(size_t)s1 * 32 + lane];
        ull x2 = h[(size_t)s2 * 32 + lane];
        ull x3 = h[(size_t)s3 * 32 + lane];
        float c0 = 1.f, c1 = 1.f, c2 = 1.f, c3 = 1.f;
        if (MODE) { c0 = g_rscale[i]; c1 = g_rscale[i + 1]; c2 = g_rscale[i + 2]; c3 = g_rscale[i + 3]; }
        acc_bf(acc, x0, c0);
        acc_bf(acc, x1, c1);
        acc_bf(acc, x2, c2);
        acc_bf(acc, x3, c3);
    }
    for (; i < end; i++) {
        ull x = h[(size_t)g_esrc[i] * 32 + lane];
        float c = MODE ? g_rscale[i] : 1.f;
        acc_bf(acc, x, c);
    }

    if (MODE) {
        reinterpret_cast<float4*>(out_)[(size_t)w * 32 + lane] = acc;
    } else {
        __nv_bfloat162 o0 = __floats2bfloat162_rn(acc.x, acc.y);
        __nv_bfloat162 o1 = __floats2bfloat162_rn(acc.z, acc.w);
        ull packed = (ull)*reinterpret_cast<unsigned*>(&o0)
                   | ((ull)*reinterpret_cast<unsigned*>(&o1) << 32);
        reinterpret_cast<ull*>(out_)[(size_t)w * 32 + lane] = packed;
    }
}

// ===========================================================================
// HMMA GEMM with bf16 hi/lo split (full fp32 effective precision):
// C = A_f32 @ W_f32 + bias;  D = Ahi@Whi + Ahi@Wlo + Alo@Whi (fp32 accum).
// mma.sync.m16n8k16. 128x128 tile, 256 threads, 8 warps (4m x 2n), warp tile
// 32x64. W transposed into smem once per block as hi+lo (row stride K+8 bf16,
// conflict-free ldmatrix). A read fp32, split hi/lo in registers, staged in
// 32-k chunks (80B rows), double-buffered via register prefetch.
// STORE=0 skips C store (last layer).
// Colsum FIX (R11): sred indexed by wr (warps wc=0/1 cover disjoint column
// halves of the same row) so all 4x128 entries are written — the R9/R10
// version indexed by wid and summed 50% stale smem.
// ===========================================================================
template <int K, int STORE>
__global__ __launch_bounds__(256)
void gemm_mma(const float* __restrict__ A, const float* __restrict__ W,
              const float* __restrict__ bias, __nv_bfloat16* __restrict__ C,
              float* __restrict__ colsum_slot, int n, int do_leaky)
{
    constexpr int WROW   = K + 8;              // bf16 elems per sWt row
    constexpr int WROWB  = WROW * 2;           // bytes
    constexpr int WSZ    = 128 * WROWB;        // one W tile (hi or lo)
    constexpr int OFF_WH = 0;
    constexpr int OFF_WL = WSZ;
    constexpr int ABUF   = 128 * 80;           // one A tile (hi or lo), one stage
    constexpr int OFF_AH = 2 * WSZ;            // 2 stages
    constexpr int OFF_AL = OFF_AH + 2 * ABUF;  // 2 stages
    constexpr int OFF_BIAS = OFF_AL + 2 * ABUF;
    constexpr int NCH    = K / 32;

    extern __shared__ char smem[];
    const uint32_t sb = smem_u32(smem);
    const int t    = threadIdx.x;
    const int lane = t & 31, wid = t >> 5;
    const int wr   = wid & 3, wc = wid >> 2;
    const int row0 = blockIdx.x * 128;

    // ---- stage full W transposed as hi+lo ----
    {
        __nv_bfloat16* wh = reinterpret_cast<__nv_bfloat16*>(smem + OFF_WH);
        __nv_bfloat16* wl = reinterpret_cast<__nv_bfloat16*>(smem + OFF_WL);
        for (int i = t * 4; i < K * 128; i += 1024) {
            float4 v = *reinterpret_cast<const float4*>(W + i);
            int k = i >> 7, nn = i & 127;
            float x[4] = {v.x, v.y, v.z, v.w};
#pragma unroll
            for (int q = 0; q < 4; q++) {
                __nv_bfloat16 h = __float2bfloat16_rn(x[q]);
                wh[(nn + q) * WROW + k] = h;
                wl[(nn + q) * WROW + k] = __float2bfloat16_rn(x[q] - __bfloat162float(h));
            }
        }
        if (t < 128) *reinterpret_cast<float*>(smem + OFF_BIAS + t * 4) = bias[t];
    }

    // A staging geometry: 1024 float4 slots per chunk (128 rows x 32 k fp32);
    // thread handles slots t + j*256, j=0..3. row = slot>>3, kq = (slot&7)*4.
    const int kq  = (t & 7) * 4;         // k offset (4 floats)
    int grows[4];
#pragma unroll
    for (int j = 0; j < 4; j++) {
        int r = (t + j * 256) >> 3;
        grows[j] = min(row0 + r, n - 1);
    }

    float acc[2][8][4];
#pragma unroll
    for (int i = 0; i < 2; i++)
#pragma unroll
        for (int j = 0; j < 8; j++)
#pragma unroll
            for (int q = 0; q < 4; q++) acc[i][j][q] = 0.f;

    // ldmatrix per-lane base addresses
    const int mat = lane >> 3, lr = lane & 7;
    const uint32_t abase = (uint32_t)((wr * 32 + (mat & 1) * 8 + lr) * 80 + (mat >> 1) * 16);
    const uint32_t bbase = (uint32_t)((wc * 64 + (mat >> 1) * 8 + lr) * WROWB + (mat & 1) * 16);

    // staging store: splits one float4 into hi/lo bf16x2 pairs and writes 8B each
    auto stage = [&](int buf, int j, float4 v) {
        int r = (t + j * 256) >> 3;
        uint2 hi = make_uint2(pk_hi(v.x, v.y), pk_hi(v.z, v.w));
        uint2 lo = make_uint2(pk_lo(v.x, v.y), pk_lo(v.z, v.w));
        *reinterpret_cast<uint2*>(smem + OFF_AH + buf * ABUF + r * 80 + kq * 2) = hi;
        *reinterpret_cast<uint2*>(smem + OFF_AL + buf * ABUF + r * 80 + kq * 2) = lo;
    };

    // ---- prologue: stage chunk 0 ----
#pragma unroll
    for (int j = 0; j < 4; j++)
        stage(0, j, *reinterpret_cast<const float4*>(A + (size_t)grows[j] * K + kq));

    float4 pv[4];
    for (int c = 0; c < NCH; c++) {
        const int cur = c & 1, nxt = cur ^ 1;
        const bool pre = (c + 1 < NCH);
        if (pre) {
            const int k0n = (c + 1) * 32;
#pragma unroll
            for (int j = 0; j < 4; j++)
                pv[j] = *reinterpret_cast<const float4*>(A + (size_t)grows[j] * K + k0n + kq);
        }
        __syncthreads();

        // ---- compute chunk c ----
        const uint32_t sAh = sb + OFF_AH + cur * ABUF + abase;
        const uint32_t sAl = sb + OFF_AL + cur * ABUF + abase;
        const uint32_t sBh = sb + OFF_WH + bbase + c * 64;   // 32 k * 2B
        const uint32_t sBl = sb + OFF_WL + bbase + c * 64;
#pragma unroll
        for (int ks = 0; ks < 2; ks++) {
            unsigned a0h[4], a1h[4], a0l[4], a1l[4];
            ldsm4(a0h, sAh + ks * 32);
            ldsm4(a1h, sAh + 1280 + ks * 32);
            ldsm4(a0l, sAl + ks * 32);
            ldsm4(a1l, sAl + 1280 + ks * 32);
#pragma unroll
            for (int np = 0; np < 4; np++) {
                unsigned bh[4], bl[4];
                ldsm4(bh, sBh + np * 16 * WROWB + ks * 32);
                ldsm4(bl, sBl + np * 16 * WROWB + ks * 32);
                // hi*hi
                mma16816(acc[0][2 * np],     a0h, bh);
                mma16816(acc[0][2 * np + 1], a0h, bh + 2);
                mma16816(acc[1][2 * np],     a1h, bh);
                mma16816(acc[1][2 * np + 1], a1h, bh + 2);
                // hi*lo
                mma16816(acc[0][2 * np],     a0h, bl);
                mma16816(acc[0][2 * np + 1], a0h, bl + 2);
                mma16816(acc[1][2 * np],     a1h, bl);
                mma16816(acc[1][2 * np + 1], a1h, bl + 2);
                // lo*hi
                mma16816(acc[0][2 * np],     a0l, bh);
                mma16816(acc[0][2 * np + 1], a0l, bh + 2);
                mma16816(acc[1][2 * np],     a1l, bh);
                mma16816(acc[1][2 * np + 1], a1l, bh + 2);
            }
        }

        if (pre) {
            __syncthreads();   // all warps done reading buffer 'nxt' from 2 chunks ago
#pragma unroll
            for (int j = 0; j < 4; j++) stage(nxt, j, pv[j]);
        }
    }

    // ---- epilogue: bias, leaky, bf16 store, colsum ----
    const float* sbias = reinterpret_cast<const float*>(smem + OFF_BIAS);
    float cs[8][2];
#pragma unroll
    for (int j = 0; j < 8; j++) { cs[j][0] = 0.f; cs[j][1] = 0.f; }

#pragma unroll
    for (int mt = 0; mt < 2; mt++) {
        const int r0 = row0 + wr * 32 + mt * 16 + (lane >> 2);
        const bool ok0 = (r0 < n), ok1 = (r0 + 8 < n);
#pragma unroll
        for (int nt = 0; nt < 8; nt++) {
            const int c0 = wc * 64 + nt * 8 + 2 * (lane & 3);
            float b0 = sbias[c0], b1 = sbias[c0 + 1];
            float v0 = acc[mt][nt][0] + b0;
            float v1 = acc[mt][nt][1] + b1;
            float v2 = acc[mt][nt][2] + b0;
            float v3 = acc[mt][nt][3] + b1;
            if (do_leaky) {
                v0 = v0 > 0.f ? v0 : 0.01f * v0;
                v1 = v1 > 0.f ? v1 : 0.01f * v1;
                v2 = v2 > 0.f ? v2 : 0.01f * v2;
                v3 = v3 > 0.f ? v3 : 0.01f * v3;
            }
            if (!ok0) { v0 = 0.f; v1 = 0.f; }
            if (!ok1) { v2 = 0.f; v3 = 0.f; }
            cs[nt][0] += v0 + v2;
            cs[nt][1] += v1 + v3;
            if (STORE) {
                if (ok0)
                    *reinterpret_cast<__nv_bfloat162*>(C + (size_t)r0 * HD + c0) =
                        __floats2bfloat162_rn(v0, v1);
                if (ok1)
                    *reinterpret_cast<__nv_bfloat162*>(C + (size_t)(r0 + 8) * HD + c0) =
                        __floats2bfloat162_rn(v2, v3);
            }
        }
    }

    // reduce colsum: shfl over the 8 row-groups (lane bits 2-4), then smem.
    // After the shfl, every lane with the same (lane&3) holds the full column
    // sum over this warp's 32 rows.
#pragma unroll
    for (int nt = 0; nt < 8; nt++) {
#pragma unroll
        for (int off = 4; off < 32; off <<= 1) {
            cs[nt][0] += __shfl_xor_sync(0xFFFFFFFFu, cs[nt][0], off);
            cs[nt][1] += __shfl_xor_sync(0xFFFFFFFFu, cs[nt][1], off);
        }
    }
    __syncthreads();
    // FIX: index by wr. Warps (wr, wc=0) and (wr, wc=1) write disjoint column
    // halves of row wr -> all 4*128 entries written, no stale smem in the sum.
    float* sred = reinterpret_cast<float*>(smem + OFF_AH);   // reuse A buffer
    if (lane < 4) {
#pragma unroll
        for (int nt = 0; nt < 8; nt++) {
            int c0 = wc * 64 + nt * 8 + 2 * lane;
            sred[wr * 128 + c0]     = cs[nt][0];
            sred[wr * 128 + c0 + 1] = cs[nt][1];
        }
    }
    __syncthreads();
    if (t < 128) {
        float s = 0.f;
#pragma unroll
        for (int r = 0; r < 4; r++) s += sred[r * 128 + t];
        atomicAdd(&colsum_slot[t], s);
    }
}

#define GEMM_SMEM_FOR(K) (2 * 128 * ((K) + 8) * 2 + 4 * 128 * 80 + 512)

// ---------------------------------------------------------------------------
// Readout: g = (colsum/N) @ Wpred + bpred ; logits = g @ Wcls + bcls ; softmax
// ---------------------------------------------------------------------------
__global__ void final_kernel(const float* __restrict__ colsum,
                             const float* __restrict__ Wpred, const float* __restrict__ bpred,
                             const float* __restrict__ Wcls,  const float* __restrict__ bcls,
                             float* __restrict__ out, float invn)
{
    __shared__ float g[HD];
    int t = threadIdx.x;
    float acc = bpred[t];
    for (int k = 0; k < (NL + 1) * HD; k++)
        acc = fmaf(colsum[k] * invn, Wpred[k * HD + t], acc);
    g[t] = acc;
    __syncthreads();
    if (t == 0) {
        float l0 = bcls[0], l1 = bcls[1];
        for (int j = 0; j < HD; j++) {
            l0 = fmaf(g[j], Wcls[j * 2 + 0], l0);
            l1 = fmaf(g[j], Wcls[j * 2 + 1], l1);
        }
        float m  = fmaxf(l0, l1);
        float e0 = expf(l0 - m), e1 = expf(l1 - m);
        float inv = 1.0f / (e0 + e1);
        out[0] = e0 * inv;
        out[1] = e1 * inv;
    }
}

// ---------------------------------------------------------------------------
extern "C" void kernel_launch(void* const* d_in, const int* in_sizes, int n_in,
                              void* d_out, int out_size)
{
    const float* node_feat = (const float*)d_in[0];
    const float* degree    = (const float*)d_in[3];
    const float* Wn        = (const float*)d_in[4];
    const float* bn        = (const float*)d_in[5];
    const float* Wgcn      = (const float*)d_in[8];
    const float* bgcn      = (const float*)d_in[9];
    const float* Wpred     = (const float*)d_in[10];
    const float* bpred     = (const float*)d_in[11];
    const float* Wcls      = (const float*)d_in[12];
    const float* bcls      = (const float*)d_in[13];
    const int*   src       = (const int*)d_in[14];
    const int*   dst       = (const int*)d_in[15];

    const int n = in_sizes[3];
    const int e = in_sizes[14];

    float *AG, *CS;
    __nv_bfloat16 *H0, *H1;
    int *CNT;
    cudaGetSymbolAddress((void**)&AG,  g_aggf);
    cudaGetSymbolAddress((void**)&H0,  g_h0);
    cudaGetSymbolAddress((void**)&H1,  g_h1);
    cudaGetSymbolAddress((void**)&CS,  g_colsum);
    cudaGetSymbolAddress((void**)&CNT, g_cnt);

    static bool init_done = false;
    static cudaStream_t s2;
    static cudaEvent_t ev_fork, ev_join;
    if (!init_done) {
        cudaFuncSetAttribute(gemm_mma<NFK, 1>, cudaFuncAttributeMaxDynamicSharedMemorySize, GEMM_SMEM_FOR(NFK));
        cudaFuncSetAttribute(gemm_mma<HD, 1>,  cudaFuncAttributeMaxDynamicSharedMemorySize, GEMM_SMEM_FOR(HD));
        cudaFuncSetAttribute(gemm_mma<HD, 0>,  cudaFuncAttributeMaxDynamicSharedMemorySize, GEMM_SMEM_FOR(HD));
        cudaStreamCreateWithFlags(&s2, cudaStreamNonBlocking);
        cudaEventCreateWithFlags(&ev_fork, cudaEventDisableTiming);
        cudaEventCreateWithFlags(&ev_join, cudaEventDisableTiming);
        init_done = true;
    }

    const int gemm_blocks   = (n + 127) / 128;
    const int edge_blocks   = (e + 255) / 256;
    const int gather_blocks = (n + 7) / 8;

    // ---- fork: CSR build on s2, overlapped with the big input GEMM ----
    cudaEventRecord(ev_fork, 0);
    cudaStreamWaitEvent(s2, ev_fork, 0);

    cudaMemsetAsync(CNT, 0, NN * sizeof(int), s2);
    hist_kernel<<<edge_blocks, 256, 0, s2>>>(dst, e);
    scan_kernel<<<1, 1024, 0, s2>>>(n);
    fill_kernel<<<edge_blocks, 256, 0, s2>>>(src, dst, degree, e);
    cudaEventRecord(ev_join, s2);

    // main stream: colsum zero + h0 = node_feat @ Wn + bn -> H0 (bf16)
    cudaMemsetAsync(CS, 0, (NL + 1) * HD * sizeof(float));
    gemm_mma<NFK, 1><<<gemm_blocks, 256, GEMM_SMEM_FOR(NFK)>>>(
        node_feat, Wn, bn, H0, CS, n, 0);

    // join: gathers need both the CSR and H0
    cudaStreamWaitEvent(0, ev_join, 0);

    // fusion: H1[v] = sum_{u->v} h0[u]
    gather_kernel<0><<<gather_blocks, 256>>>((const ull*)H0, H1, n);

    // layer 0: gather H1 -> AG (fp32), gemm AG -> H0
    gather_kernel<1><<<gather_blocks, 256>>>((const ull*)H1, AG, n);
    gemm_mma<HD, 1><<<gemm_blocks, 256, GEMM_SMEM_FOR(HD)>>>(
        AG, Wgcn, bgcn, H0, CS + 1 * HD, n, 1);

    // layer 1: gather H0 -> AG, gemm AG -> H1
    gather_kernel<1><<<gather_blocks, 256>>>((const ull*)H0, AG, n);
    gemm_mma<HD, 1><<<gemm_blocks, 256, GEMM_SMEM_FOR(HD)>>>(
        AG, Wgcn, bgcn, H1, CS + 2 * HD, n, 1);

    // layer 2: gather H1 -> AG, gemm colsum-only (h3 never read again)
    gather_kernel<1><<<gather_blocks, 256>>>((const ull*)H1, AG, n);
    gemm_mma<HD, 0><<<gemm_blocks, 256, GEMM_SMEM_FOR(HD)>>>(
        AG, Wgcn, bgcn, (__nv_bfloat16*)nullptr, CS + 3 * HD, n, 1);

    final_kernel<<<1, HD>>>(CS, Wpred, bpred, Wcls, bcls, (float*)d_out, 1.0f / (float)n);
}